// round 2
// baseline (speedup 1.0000x reference)
#include <cuda_runtime.h>
#include <cuda_bf16.h>
#include <math.h>

#define BB 16
#define LL 512
#define DD 768
#define HH 4
#define AA 100
#define DK 25
#define PP 3
#define EPS 1e-6f

// ---------------- scratch ----------------
__device__ float g_seqn[BB * LL * DD];
__device__ float g_x   [BB * LL * AA];
__device__ float g_q   [BB * LL * AA];
__device__ float g_k   [BB * LL * AA];
__device__ float g_scores[(size_t)BB * HH * LL * LL];
__device__ float g_adjm[(size_t)BB * LL * LL];
__device__ float g_adjc[(size_t)BB * LL * LL];
__device__ float g_Ax  [BB * LL * AA];
__device__ float g_x1  [BB * LL * AA];
__device__ float g_x2  [BB * LL * AA];
__device__ float g_feats[BB * LL * 3 * AA];
__device__ float g_node[BB * LL * AA];
__device__ float g_pooled[BB * AA];
__device__ float g_cbuf[HH];
__device__ float g_b1m[AA];
__device__ float g_b2m[AA];
__device__ float g_bm[1];
__device__ float g_um[BB * LL];
__device__ float g_vm[BB * LL];
__device__ float g_S[BB * AA];
__device__ float g_U[BB * AA];

__device__ __forceinline__ unsigned tf32cvt(float x) {
    unsigned u;
    asm("cvt.rna.tf32.f32 %0, %1;" : "=r"(u) : "f"(x));
    return u;
}

__device__ __forceinline__ void mma_tf32(float* c, unsigned a0, unsigned a1,
                                         unsigned a2, unsigned a3,
                                         unsigned b0, unsigned b1) {
    asm volatile(
        "mma.sync.aligned.m16n8k8.row.col.f32.tf32.tf32.f32 "
        "{%0,%1,%2,%3}, {%4,%5,%6,%7}, {%8,%9}, {%0,%1,%2,%3};"
        : "+f"(c[0]), "+f"(c[1]), "+f"(c[2]), "+f"(c[3])
        : "r"(a0), "r"(a1), "r"(a2), "r"(a3), "r"(b0), "r"(b1));
}

// ---------------- precompute ----------------
__global__ void pre_kernel(const float* __restrict__ Wx_w, const float* __restrict__ Wx_b)
{
    int t = threadIdx.x;
    const int LDW = HH + 2 * AA;
    if (t < HH) {
        float s = 0.f;
        for (int g = 0; g < HH; g++) s += Wx_w[g * LDW + t];
        g_cbuf[t] = s * 0.25f;
    }
    if (t < AA) {
        float s1 = 0.f, s2 = 0.f;
        for (int g = 0; g < HH; g++) {
            s1 += Wx_w[g * LDW + HH + t];
            s2 += Wx_w[g * LDW + HH + AA + t];
        }
        g_b1m[t] = s1 * 0.25f;
        g_b2m[t] = s2 * 0.25f;
    }
    if (t == 0) {
        float s = 0.f;
        for (int g = 0; g < HH; g++) s += Wx_b[g];
        g_bm[0] = s * 0.25f;
    }
}

// ---------------- LayerNorm ----------------
__global__ void ln_kernel(const float* __restrict__ x, const float* __restrict__ a,
                          const float* __restrict__ bvec)
{
    int row = blockIdx.x;
    const float* xr = x + (size_t)row * DD;
    float* yr = g_seqn + (size_t)row * DD;
    int t = threadIdx.x;
    __shared__ float red[16];
    float v0 = xr[t], v1 = xr[t + 256], v2 = xr[t + 512];
    float s = v0 + v1 + v2;
    float ss = v0 * v0 + v1 * v1 + v2 * v2;
    for (int o = 16; o; o >>= 1) {
        s  += __shfl_xor_sync(0xffffffffu, s, o);
        ss += __shfl_xor_sync(0xffffffffu, ss, o);
    }
    int w = t >> 5;
    if ((t & 31) == 0) { red[w] = s; red[8 + w] = ss; }
    __syncthreads();
    float S = 0.f, SS = 0.f;
    #pragma unroll
    for (int i = 0; i < 8; i++) { S += red[i]; SS += red[8 + i]; }
    float mean = S / (float)DD;
    float var = (SS - (float)DD * mean * mean) / (float)(DD - 1);
    var = fmaxf(var, 0.f);
    float inv = 1.f / (sqrtf(var) + EPS);
    yr[t]       = a[t]       * (v0 - mean) * inv + bvec[t];
    yr[t + 256] = a[t + 256] * (v1 - mean) * inv + bvec[t + 256];
    yr[t + 512] = a[t + 512] * (v2 - mean) * inv + bvec[t + 512];
}

// ============ TF32 tensor-core GEMM: C = act(A(M,K) @ B(N,K)^T + bias) ============
// BM=64, BN=112 (N<=112), BK=16, 256 threads (8 warps: 4m x 2n), warp tile 16x56
__global__ void gemm_nt_tf32(const float* __restrict__ A, const float* __restrict__ Bm,
                             const float* __restrict__ bias, float* __restrict__ C,
                             int M, int N, int K, int act)
{
    __shared__ unsigned As[16][68];    // [k][m]
    __shared__ unsigned Bs[16][116];   // [k][n]
    int t = threadIdx.x;
    int lane = t & 31, warp = t >> 5;
    int wm = warp & 3, wn = warp >> 2;
    int g = lane >> 2, tg = lane & 3;
    int m0 = blockIdx.y * 64;

    float acc[7][4];
    #pragma unroll
    for (int j = 0; j < 7; j++)
        #pragma unroll
        for (int i = 0; i < 4; i++) acc[j][i] = 0.f;

    int arow = t >> 2, akg = (t & 3) * 4;
    const float* Aptr = A + (size_t)(m0 + arow) * K + akg;

    for (int k0 = 0; k0 < K; k0 += 16) {
        // A tile: 64x16, one float4 per thread
        if (k0 + 16 <= K) {
            float4 a4 = *(const float4*)(Aptr + k0);
            As[akg + 0][arow] = tf32cvt(a4.x);
            As[akg + 1][arow] = tf32cvt(a4.y);
            As[akg + 2][arow] = tf32cvt(a4.z);
            As[akg + 3][arow] = tf32cvt(a4.w);
        } else {
            #pragma unroll
            for (int i = 0; i < 4; i++) {
                int kk = k0 + akg + i;
                As[akg + i][arow] = (kk < K) ? tf32cvt(Aptr[k0 + i]) : 0u;
            }
        }
        // B tile: B is (N,K) row-major -> Bs[k][n]
        #pragma unroll
        for (int it = 0; it < 7; it++) {
            int idx = t + it * 256;
            int n = idx >> 4, k = idx & 15;
            float v = (n < N && k0 + k < K) ? Bm[(size_t)n * K + k0 + k] : 0.f;
            Bs[k][n] = tf32cvt(v);
        }
        __syncthreads();
        #pragma unroll
        for (int ks = 0; ks < 2; ks++) {
            int kb = ks * 8;
            unsigned a0 = As[kb + tg][wm * 16 + g];
            unsigned a1 = As[kb + tg][wm * 16 + g + 8];
            unsigned a2 = As[kb + tg + 4][wm * 16 + g];
            unsigned a3 = As[kb + tg + 4][wm * 16 + g + 8];
            #pragma unroll
            for (int j = 0; j < 7; j++) {
                unsigned b0 = Bs[kb + tg][wn * 56 + j * 8 + g];
                unsigned b1 = Bs[kb + tg + 4][wn * 56 + j * 8 + g];
                mma_tf32(acc[j], a0, a1, a2, a3, b0, b1);
            }
        }
        __syncthreads();
    }
    int r0 = m0 + wm * 16 + g, r1 = r0 + 8;
    #pragma unroll
    for (int j = 0; j < 7; j++) {
        int c0 = wn * 56 + j * 8 + tg * 2;
        if (c0 < N) {
            float v0 = acc[j][0] + bias[c0];
            float v2 = acc[j][2] + bias[c0];
            if (act) { v0 = fmaxf(v0, 0.f); v2 = fmaxf(v2, 0.f); }
            C[(size_t)r0 * N + c0] = v0;
            C[(size_t)r1 * N + c0] = v2;
        }
        if (c0 + 1 < N) {
            float v1 = acc[j][1] + bias[c0 + 1];
            float v3 = acc[j][3] + bias[c0 + 1];
            if (act) { v1 = fmaxf(v1, 0.f); v3 = fmaxf(v3, 0.f); }
            C[(size_t)r0 * N + c0 + 1] = v1;
            C[(size_t)r1 * N + c0 + 1] = v3;
        }
    }
}

// ============ TF32 batched NN GEMM: C[b] = A[b](M,K) @ B[b](K,N) + rank-1 ============
__global__ void gemm_nn_b_tf32(const float* __restrict__ Ag, const float* __restrict__ Bg,
                               float* __restrict__ Cg,
                               int M, int N, int K, int sA, int sB, int sC,
                               const float* __restrict__ U, const float* __restrict__ S,
                               const float* __restrict__ vm, const float* __restrict__ bmp)
{
    int b = blockIdx.z;
    const float* A = Ag + (size_t)b * sA;
    const float* Bm = Bg + (size_t)b * sB;
    float* C = Cg + (size_t)b * sC;
    __shared__ unsigned As[16][68];
    __shared__ unsigned Bs[16][116];
    int t = threadIdx.x;
    int lane = t & 31, warp = t >> 5;
    int wm = warp & 3, wn = warp >> 2;
    int g = lane >> 2, tg = lane & 3;
    int m0 = blockIdx.y * 64;

    float acc[7][4];
    #pragma unroll
    for (int j = 0; j < 7; j++)
        #pragma unroll
        for (int i = 0; i < 4; i++) acc[j][i] = 0.f;

    int arow = t >> 2, akg = (t & 3) * 4;
    const float* Aptr = A + (size_t)(m0 + arow) * K + akg;

    for (int k0 = 0; k0 < K; k0 += 16) {
        float4 a4 = *(const float4*)(Aptr + k0);   // K=512, always aligned/full
        As[akg + 0][arow] = tf32cvt(a4.x);
        As[akg + 1][arow] = tf32cvt(a4.y);
        As[akg + 2][arow] = tf32cvt(a4.z);
        As[akg + 3][arow] = tf32cvt(a4.w);
        #pragma unroll
        for (int it = 0; it < 7; it++) {
            int idx = t + it * 256;
            int k = idx / 112, n = idx - k * 112;
            float v = (n < N) ? Bm[(size_t)(k0 + k) * N + n] : 0.f;
            Bs[k][n] = tf32cvt(v);
        }
        __syncthreads();
        #pragma unroll
        for (int ks = 0; ks < 2; ks++) {
            int kb = ks * 8;
            unsigned a0 = As[kb + tg][wm * 16 + g];
            unsigned a1 = As[kb + tg][wm * 16 + g + 8];
            unsigned a2 = As[kb + tg + 4][wm * 16 + g];
            unsigned a3 = As[kb + tg + 4][wm * 16 + g + 8];
            #pragma unroll
            for (int j = 0; j < 7; j++) {
                unsigned b0 = Bs[kb + tg][wn * 56 + j * 8 + g];
                unsigned b1 = Bs[kb + tg + 4][wn * 56 + j * 8 + g];
                mma_tf32(acc[j], a0, a1, a2, a3, b0, b1);
            }
        }
        __syncthreads();
    }
    int r0 = m0 + wm * 16 + g, r1 = r0 + 8;
    float e0 = 0.f, e1 = 0.f;
    if (U != nullptr) {
        float bmv = bmp[0];
        e0 = vm[b * LL + r0] + bmv;
        e1 = vm[b * LL + r1] + bmv;
    }
    #pragma unroll
    for (int j = 0; j < 7; j++) {
        #pragma unroll
        for (int jj = 0; jj < 2; jj++) {
            int col = wn * 56 + j * 8 + tg * 2 + jj;
            if (col >= N) continue;
            float v0 = acc[j][jj], v1 = acc[j][2 + jj];
            if (U != nullptr) {
                float uu = U[b * AA + col], ssv = S[b * AA + col];
                v0 += uu + e0 * ssv;
                v1 += uu + e1 * ssv;
            }
            C[(size_t)r0 * N + col] = v0;
            C[(size_t)r1 * N + col] = v1;
        }
    }
}

// ---------------- scores ----------------
__global__ void scores_kernel(const float* __restrict__ syn, const int* __restrict__ src_mask)
{
    int bh = blockIdx.z;
    int b = bh >> 2, h = bh & 3;
    int i0 = blockIdx.y * 32, j0 = blockIdx.x * 32;
    __shared__ float qs[32][26], ks[32][26];
    int t = threadIdx.x;
    for (int idx = t; idx < 32 * DK; idx += 256) {
        int r = idx / DK, c = idx % DK;
        qs[r][c] = g_q[(size_t)(b * LL + i0 + r) * AA + h * DK + c];
        ks[r][c] = g_k[(size_t)(b * LL + j0 + r) * AA + h * DK + c];
    }
    __syncthreads();
    int i = t >> 3, jb = (t & 7) * 4;
    float qr[DK];
    #pragma unroll
    for (int c = 0; c < DK; c++) qr[c] = qs[i][c];
    #pragma unroll
    for (int jj = 0; jj < 4; jj++) {
        int j = jb + jj;
        float acc = 0.f;
        #pragma unroll
        for (int c = 0; c < DK; c++) acc += qr[c] * ks[j][c];
        float v = acc * 0.2f;
        if (src_mask[b * LL + j0 + j] == 0) v = -1e9f;
        size_t off = ((size_t)(b * HH + h) * LL + (i0 + i)) * LL + (j0 + j);
        v += syn[off];
        g_scores[off] = v;
    }
}

// ---------------- softmax + head folding ----------------
__global__ void softmax_combine_kernel()
{
    int bi = blockIdx.x;
    int t = threadIdx.x;
    __shared__ float red[16];
    float am0 = 0.f, am1 = 0.f, ac0 = 0.f, ac1 = 0.f;
    for (int h = 0; h < HH; h++) {
        size_t base = ((size_t)((bi >> 9) * HH + h) * LL + (bi & 511)) * LL;
        float v0 = g_scores[base + t];
        float v1 = g_scores[base + t + 256];
        float m = fmaxf(v0, v1);
        for (int o = 16; o; o >>= 1) m = fmaxf(m, __shfl_xor_sync(0xffffffffu, m, o));
        if ((t & 31) == 0) red[t >> 5] = m;
        __syncthreads();
        m = red[0];
        #pragma unroll
        for (int i = 1; i < 8; i++) m = fmaxf(m, red[i]);
        float e0 = __expf(v0 - m), e1 = __expf(v1 - m);
        float s = e0 + e1;
        for (int o = 16; o; o >>= 1) s += __shfl_xor_sync(0xffffffffu, s, o);
        if ((t & 31) == 0) red[8 + (t >> 5)] = s;
        __syncthreads();
        s = 0.f;
        #pragma unroll
        for (int i = 0; i < 8; i++) s += red[8 + i];
        float inv = 1.f / s;
        float ch = g_cbuf[h];
        am0 += 0.25f * e0 * inv; am1 += 0.25f * e1 * inv;
        ac0 += ch * e0 * inv;    ac1 += ch * e1 * inv;
        __syncthreads();
    }
    size_t ob = (size_t)bi * LL;
    g_adjm[ob + t] = am0; g_adjm[ob + t + 256] = am1;
    g_adjc[ob + t] = ac0; g_adjc[ob + t + 256] = ac1;
}

// ---------------- um/vm ----------------
__global__ void umvm_kernel()
{
    int w = threadIdx.x >> 5, lane = threadIdx.x & 31;
    int row = blockIdx.x * 8 + w;
    const float* xr = g_x1 + (size_t)row * AA;
    float u = 0.f, v = 0.f;
    for (int c = lane; c < AA; c += 32) {
        float xv = xr[c];
        u += xv * g_b1m[c];
        v += xv * g_b2m[c];
    }
    for (int o = 16; o; o >>= 1) {
        u += __shfl_xor_sync(0xffffffffu, u, o);
        v += __shfl_xor_sync(0xffffffffu, v, o);
    }
    if (lane == 0) { g_um[row] = u; g_vm[row] = v; }
}

// ---------------- S / U ----------------
__global__ void su_kernel()
{
    int b = blockIdx.x;
    int d = threadIdx.x;
    if (d >= AA) return;
    float s = 0.f, u = 0.f;
    for (int j = 0; j < LL; j++) {
        float xv = g_x1[(size_t)(b * LL + j) * AA + d];
        s += xv;
        u += g_um[b * LL + j] * xv;
    }
    g_S[b * AA + d] = s;
    g_U[b * AA + d] = u;
}

// ---------------- concat ----------------
__global__ void concat_kernel()
{
    int idx = blockIdx.x * blockDim.x + threadIdx.x;
    if (idx >= BB * LL * AA) return;
    int row = idx / AA, d = idx % AA;
    g_feats[(size_t)row * (3 * AA) + d]          = g_x [idx];
    g_feats[(size_t)row * (3 * AA) + AA + d]     = g_x1[idx];
    g_feats[(size_t)row * (3 * AA) + 2 * AA + d] = g_x2[idx];
}

// ---------------- pool ----------------
__global__ void pool_kernel(const int* __restrict__ mask_ids)
{
    int b = blockIdx.x;
    __shared__ int redc[128];
    int t = threadIdx.x;
    int cnt = 0;
    for (int j = t; j < LL; j += 128) cnt += mask_ids[b * LL + j];
    redc[t] = cnt;
    __syncthreads();
    for (int o = 64; o; o >>= 1) { if (t < o) redc[t] += redc[t + o]; __syncthreads(); }
    float vl = fmaxf((float)redc[0], 1.f);
    if (t < AA) {
        float s = 0.f;
        for (int j = 0; j < LL; j++) s += g_node[(size_t)(b * LL + j) * AA + t];
        g_pooled[b * AA + t] = s / vl;
    }
}

// ---------------- logits ----------------
__global__ void logits_kernel(const float* __restrict__ cw, const float* __restrict__ cb,
                              float* __restrict__ out)
{
    int t = threadIdx.x;
    if (t >= BB * PP) return;
    int b = t / PP, p = t % PP;
    float s = cb[p];
    for (int d = 0; d < AA; d++) s += g_pooled[b * AA + d] * cw[p * AA + d];
    out[t] = s;
}

// ================================================================
extern "C" void kernel_launch(void* const* d_in, const int* in_sizes, int n_in,
                              void* d_out, int out_size)
{
    const float* seq     = (const float*)d_in[0];
    const float* syn     = (const float*)d_in[1];
    const float* ln_a    = (const float*)d_in[2];
    const float* ln_b    = (const float*)d_in[3];
    const float* Wxx_w   = (const float*)d_in[4];
    const float* Wxx_b   = (const float*)d_in[5];
    const float* q_w     = (const float*)d_in[6];
    const float* q_b     = (const float*)d_in[7];
    const float* k_w     = (const float*)d_in[8];
    const float* k_b     = (const float*)d_in[9];
    const float* W_w     = (const float*)d_in[10];
    const float* W_b     = (const float*)d_in[11];
    const float* Wx_w    = (const float*)d_in[12];
    const float* Wx_b    = (const float*)d_in[13];
    const float* agg_w   = (const float*)d_in[14];
    const float* agg_b   = (const float*)d_in[15];
    const float* cls_w   = (const float*)d_in[16];
    const float* cls_b   = (const float*)d_in[17];
    const int*   mask_ids= (const int*)d_in[18];
    const int*   src_mask= (const int*)d_in[19];
    float* out = (float*)d_out;

    float *p_seqn, *p_x, *p_Ax, *p_x1, *p_x2, *p_feats, *p_node;
    float *p_adjm, *p_adjc, *p_U, *p_S, *p_vm, *p_bm, *p_q, *p_k;
    cudaGetSymbolAddress((void**)&p_seqn, g_seqn);
    cudaGetSymbolAddress((void**)&p_x,    g_x);
    cudaGetSymbolAddress((void**)&p_q,    g_q);
    cudaGetSymbolAddress((void**)&p_k,    g_k);
    cudaGetSymbolAddress((void**)&p_Ax,   g_Ax);
    cudaGetSymbolAddress((void**)&p_x1,   g_x1);
    cudaGetSymbolAddress((void**)&p_x2,   g_x2);
    cudaGetSymbolAddress((void**)&p_feats,g_feats);
    cudaGetSymbolAddress((void**)&p_node, g_node);
    cudaGetSymbolAddress((void**)&p_adjm, g_adjm);
    cudaGetSymbolAddress((void**)&p_adjc, g_adjc);
    cudaGetSymbolAddress((void**)&p_U,    g_U);
    cudaGetSymbolAddress((void**)&p_S,    g_S);
    cudaGetSymbolAddress((void**)&p_vm,   g_vm);
    cudaGetSymbolAddress((void**)&p_bm,   g_bm);

    const int MROWS = BB * LL;              // 8192
    dim3 nt_grid(1, MROWS / 64);            // 128 blocks
    dim3 nn_grid(1, LL / 64, BB);           // 128 blocks

    pre_kernel<<<1, 128>>>(Wx_w, Wx_b);
    ln_kernel<<<MROWS, 256>>>(seq, ln_a, ln_b);

    gemm_nt_tf32<<<nt_grid, 256>>>(p_seqn, Wxx_w, Wxx_b, p_x, MROWS, AA, DD, 0);
    gemm_nt_tf32<<<nt_grid, 256>>>(p_x, q_w, q_b, p_q, MROWS, AA, AA, 0);
    gemm_nt_tf32<<<nt_grid, 256>>>(p_x, k_w, k_b, p_k, MROWS, AA, AA, 0);

    scores_kernel<<<dim3(LL / 32, LL / 32, BB * HH), 256>>>(syn, src_mask);
    softmax_combine_kernel<<<MROWS, 256>>>();

    gemm_nn_b_tf32<<<nn_grid, 256>>>(p_adjm, p_x, p_Ax,
        LL, AA, LL, LL * LL, LL * AA, LL * AA, nullptr, nullptr, nullptr, nullptr);
    gemm_nt_tf32<<<nt_grid, 256>>>(p_Ax, W_w, W_b, p_x1, MROWS, AA, AA, 1);

    umvm_kernel<<<MROWS / 8, 256>>>();
    su_kernel<<<BB, 128>>>();

    gemm_nn_b_tf32<<<nn_grid, 256>>>(p_adjc, p_x1, p_Ax,
        LL, AA, LL, LL * LL, LL * AA, LL * AA, p_U, p_S, p_vm, p_bm);
    gemm_nt_tf32<<<nt_grid, 256>>>(p_Ax, W_w, W_b, p_x2, MROWS, AA, AA, 1);

    concat_kernel<<<(BB * LL * AA + 255) / 256, 256>>>();
    gemm_nt_tf32<<<nt_grid, 256>>>(p_feats, agg_w, agg_b, p_node, MROWS, AA, 3 * AA, 1);

    pool_kernel<<<BB, 128>>>(mask_ids);
    logits_kernel<<<1, 64>>>(cls_w, cls_b, out);
}

// round 4
// speedup vs baseline: 2.6328x; 2.6328x over previous
#include <cuda_runtime.h>
#include <cuda_bf16.h>
#include <math.h>

#define BB 16
#define LL 512
#define DD 768
#define HH 4
#define AA 100
#define DK 25
#define PP 3
#define EPS 1e-6f

#define BM 32
#define BN 112
#define AST 20
#define BST 20
#define BNNST 120

// ---------------- scratch ----------------
__device__ float g_seqn[BB * LL * DD];
__device__ float g_x   [BB * LL * AA];
__device__ float g_q   [BB * LL * AA];
__device__ float g_k   [BB * LL * AA];
__device__ float g_scores[(size_t)BB * HH * LL * LL];
__device__ float g_adjm[(size_t)BB * LL * LL];
__device__ float g_adjc[(size_t)BB * LL * LL];
__device__ float g_Ax  [BB * LL * AA];
__device__ float g_x1  [BB * LL * AA];
__device__ float g_x2  [BB * LL * AA];
__device__ float g_feats[BB * LL * 3 * AA];
__device__ float g_node[BB * LL * AA];
__device__ float g_pooled[BB * AA];
__device__ float g_cbuf[HH];
__device__ float g_b1m[AA];
__device__ float g_b2m[AA];
__device__ float g_bm[1];
__device__ float g_um[BB * LL];
__device__ float g_vm[BB * LL];
__device__ float g_S[BB * AA];
__device__ float g_U[BB * AA];

__device__ __forceinline__ unsigned tf32cvt(float x) {
    unsigned u;
    asm("cvt.rna.tf32.f32 %0, %1;" : "=r"(u) : "f"(x));
    return u;
}

__device__ __forceinline__ void mma_tf32(float* c, unsigned a0, unsigned a1,
                                         unsigned a2, unsigned a3,
                                         unsigned b0, unsigned b1) {
    asm volatile(
        "mma.sync.aligned.m16n8k8.row.col.f32.tf32.tf32.f32 "
        "{%0,%1,%2,%3}, {%4,%5,%6,%7}, {%8,%9}, {%0,%1,%2,%3};"
        : "+f"(c[0]), "+f"(c[1]), "+f"(c[2]), "+f"(c[3])
        : "r"(a0), "r"(a1), "r"(a2), "r"(a3), "r"(b0), "r"(b1));
}

__device__ __forceinline__ void cp16(unsigned dst, const void* src, int bytes) {
    asm volatile("cp.async.cg.shared.global [%0], [%1], 16, %2;\n"
                 :: "r"(dst), "l"(src), "r"(bytes));
}
__device__ __forceinline__ void cp_commit() {
    asm volatile("cp.async.commit_group;\n");
}
__device__ __forceinline__ void cp_wait1() {
    asm volatile("cp.async.wait_group 1;\n");
}

// ---------------- precompute ----------------
__global__ void pre_kernel(const float* __restrict__ Wx_w, const float* __restrict__ Wx_b)
{
    int t = threadIdx.x;
    const int LDW = HH + 2 * AA;
    if (t < HH) {
        float s = 0.f;
        for (int g = 0; g < HH; g++) s += Wx_w[g * LDW + t];
        g_cbuf[t] = s * 0.25f;
    }
    if (t < AA) {
        float s1 = 0.f, s2 = 0.f;
        for (int g = 0; g < HH; g++) {
            s1 += Wx_w[g * LDW + HH + t];
            s2 += Wx_w[g * LDW + HH + AA + t];
        }
        g_b1m[t] = s1 * 0.25f;
        g_b2m[t] = s2 * 0.25f;
    }
    if (t == 0) {
        float s = 0.f;
        for (int g = 0; g < HH; g++) s += Wx_b[g];
        g_bm[0] = s * 0.25f;
    }
}

// ---------------- LayerNorm ----------------
__global__ void ln_kernel(const float* __restrict__ x, const float* __restrict__ a,
                          const float* __restrict__ bvec)
{
    int row = blockIdx.x;
    const float* xr = x + (size_t)row * DD;
    float* yr = g_seqn + (size_t)row * DD;
    int t = threadIdx.x;
    __shared__ float red[16];
    float v0 = xr[t], v1 = xr[t + 256], v2 = xr[t + 512];
    float s = v0 + v1 + v2;
    float ss = v0 * v0 + v1 * v1 + v2 * v2;
    for (int o = 16; o; o >>= 1) {
        s  += __shfl_xor_sync(0xffffffffu, s, o);
        ss += __shfl_xor_sync(0xffffffffu, ss, o);
    }
    int w = t >> 5;
    if ((t & 31) == 0) { red[w] = s; red[8 + w] = ss; }
    __syncthreads();
    float S = 0.f, SS = 0.f;
    #pragma unroll
    for (int i = 0; i < 8; i++) { S += red[i]; SS += red[8 + i]; }
    float mean = S / (float)DD;
    float var = (SS - (float)DD * mean * mean) / (float)(DD - 1);
    var = fmaxf(var, 0.f);
    float inv = 1.f / (sqrtf(var) + EPS);
    yr[t]       = a[t]       * (v0 - mean) * inv + bvec[t];
    yr[t + 256] = a[t + 256] * (v1 - mean) * inv + bvec[t + 256];
    yr[t + 512] = a[t + 512] * (v2 - mean) * inv + bvec[t + 512];
}

// ============ TF32 NT GEMM: C = act(A(M,K) @ B(N,K)^T + bias) ============
__global__ __launch_bounds__(128) void gemm_nt_tc(
    const float* __restrict__ A, const float* __restrict__ Bm,
    const float* __restrict__ bias, float* __restrict__ C,
    int M, int N, int K, int act)
{
    __shared__ float As[2][BM * AST];
    __shared__ float Bs[2][BN * BST];
    int t = threadIdx.x;
    int lane = t & 31, warp = t >> 5;
    int wm = warp & 1, wn = warp >> 1;
    int g = lane >> 2, tg = lane & 3;
    int m0 = blockIdx.y * BM;

    unsigned sA = (unsigned)__cvta_generic_to_shared(&As[0][0]);
    unsigned sB = (unsigned)__cvta_generic_to_shared(&Bs[0][0]);

    float acc[7][4];
    #pragma unroll
    for (int j = 0; j < 7; j++)
        #pragma unroll
        for (int i = 0; i < 4; i++) acc[j][i] = 0.f;

    const int arow = t >> 2, ac = t & 3;
    int nk = (K + 15) >> 4;

    {
        int rem = (K - ac * 4) * 4;
        int bytes = rem >= 16 ? 16 : (rem > 0 ? rem : 0);
        cp16(sA + (arow * AST + ac * 4) * 4,
             A + (size_t)(m0 + arow) * K + ac * 4, bytes);
        #pragma unroll
        for (int i = 0; i < 4; i++) {
            int idx = t + i * 128;
            if (idx < BN * 4) {
                int row = idx >> 2, c = idx & 3;
                int rem2 = (K - c * 4) * 4;
                int bytes2 = (row < N) ? (rem2 >= 16 ? 16 : (rem2 > 0 ? rem2 : 0)) : 0;
                cp16(sB + (row * BST + c * 4) * 4,
                     Bm + (size_t)(row < N ? row : 0) * K + c * 4, bytes2);
            }
        }
    }
    cp_commit();

    for (int it = 0; it < nk; it++) {
        if (it + 1 < nk) {
            int k0 = (it + 1) << 4;
            int s = (it + 1) & 1;
            int rem = (K - k0 - ac * 4) * 4;
            int bytes = rem >= 16 ? 16 : (rem > 0 ? rem : 0);
            cp16(sA + (s * BM * AST + arow * AST + ac * 4) * 4,
                 A + (size_t)(m0 + arow) * K + k0 + ac * 4, bytes);
            #pragma unroll
            for (int i = 0; i < 4; i++) {
                int idx = t + i * 128;
                if (idx < BN * 4) {
                    int row = idx >> 2, c = idx & 3;
                    int rem2 = (K - k0 - c * 4) * 4;
                    int bytes2 = (row < N) ? (rem2 >= 16 ? 16 : (rem2 > 0 ? rem2 : 0)) : 0;
                    cp16(sB + (s * BN * BST + row * BST + c * 4) * 4,
                         Bm + (size_t)(row < N ? row : 0) * K + k0 + c * 4, bytes2);
                }
            }
        }
        cp_commit();
        cp_wait1();
        __syncthreads();
        int s = it & 1;
        const float* as = &As[s][0];
        const float* bs = &Bs[s][0];
        #pragma unroll
        for (int kb = 0; kb < 16; kb += 8) {
            int ar = (wm * 16 + g) * AST + kb + tg;
            unsigned a0 = tf32cvt(as[ar]);
            unsigned a1 = tf32cvt(as[ar + 8 * AST]);
            unsigned a2 = tf32cvt(as[ar + 4]);
            unsigned a3 = tf32cvt(as[ar + 8 * AST + 4]);
            #pragma unroll
            for (int j = 0; j < 7; j++) {
                int br = (wn * 56 + j * 8 + g) * BST + kb + tg;
                unsigned b0 = tf32cvt(bs[br]);
                unsigned b1 = tf32cvt(bs[br + 4]);
                mma_tf32(acc[j], a0, a1, a2, a3, b0, b1);
            }
        }
        __syncthreads();
    }

    int r0 = m0 + wm * 16 + g, r1 = r0 + 8;
    #pragma unroll
    for (int j = 0; j < 7; j++) {
        int c0 = wn * 56 + j * 8 + tg * 2;
        if (c0 < N) {
            float b0 = bias[c0];
            float v0 = acc[j][0] + b0, v2 = acc[j][2] + b0;
            if (act) { v0 = fmaxf(v0, 0.f); v2 = fmaxf(v2, 0.f); }
            C[(size_t)r0 * N + c0] = v0;
            C[(size_t)r1 * N + c0] = v2;
        }
        if (c0 + 1 < N) {
            float b1 = bias[c0 + 1];
            float v1 = acc[j][1] + b1, v3 = acc[j][3] + b1;
            if (act) { v1 = fmaxf(v1, 0.f); v3 = fmaxf(v3, 0.f); }
            C[(size_t)r0 * N + c0 + 1] = v1;
            C[(size_t)r1 * N + c0 + 1] = v3;
        }
    }
}

// ============ TF32 batched NN GEMM: C[b] = A[b](512,512) @ B[b](512,100) + rank-1 ============
__global__ __launch_bounds__(128) void gemm_nn_b_tc(
    const float* __restrict__ Ag, const float* __restrict__ Bg,
    float* __restrict__ Cg, int N,
    const float* __restrict__ U, const float* __restrict__ S,
    const float* __restrict__ vm, const float* __restrict__ bmp)
{
    const int K = LL;
    int b = blockIdx.z;
    const float* A = Ag + (size_t)b * LL * LL;
    const float* Bm = Bg + (size_t)b * LL * AA;
    float* C = Cg + (size_t)b * LL * AA;
    __shared__ float As[2][BM * AST];
    __shared__ float Bs[2][16 * BNNST];
    int t = threadIdx.x;
    int lane = t & 31, warp = t >> 5;
    int wm = warp & 1, wn = warp >> 1;
    int g = lane >> 2, tg = lane & 3;
    int m0 = blockIdx.y * BM;

    unsigned sA = (unsigned)__cvta_generic_to_shared(&As[0][0]);
    unsigned sB = (unsigned)__cvta_generic_to_shared(&Bs[0][0]);

    float acc[7][4];
    #pragma unroll
    for (int j = 0; j < 7; j++)
        #pragma unroll
        for (int i = 0; i < 4; i++) acc[j][i] = 0.f;

    const int arow = t >> 2, ac = t & 3;
    int nk = K >> 4;

    {
        cp16(sA + (arow * AST + ac * 4) * 4,
             A + (size_t)(m0 + arow) * K + ac * 4, 16);
        #pragma unroll
        for (int i = 0; i < 4; i++) {
            int idx = t + i * 128;
            if (idx < 16 * 28) {
                int k = idx / 28, c = idx - k * 28;
                int bytes = (4 * c < N) ? ((N - 4 * c) >= 4 ? 16 : (N - 4 * c) * 4) : 0;
                cp16(sB + (k * BNNST + c * 4) * 4,
                     Bm + (size_t)k * N + c * 4, bytes);
            }
        }
    }
    cp_commit();

    for (int it = 0; it < nk; it++) {
        if (it + 1 < nk) {
            int k0 = (it + 1) << 4;
            int s = (it + 1) & 1;
            cp16(sA + (s * BM * AST + arow * AST + ac * 4) * 4,
                 A + (size_t)(m0 + arow) * K + k0 + ac * 4, 16);
            #pragma unroll
            for (int i = 0; i < 4; i++) {
                int idx = t + i * 128;
                if (idx < 16 * 28) {
                    int k = idx / 28, c = idx - k * 28;
                    int bytes = (4 * c < N) ? ((N - 4 * c) >= 4 ? 16 : (N - 4 * c) * 4) : 0;
                    cp16(sB + (s * 16 * BNNST + k * BNNST + c * 4) * 4,
                         Bm + (size_t)(k0 + k) * N + c * 4, bytes);
                }
            }
        }
        cp_commit();
        cp_wait1();
        __syncthreads();
        int s = it & 1;
        const float* as = &As[s][0];
        const float* bs = &Bs[s][0];
        #pragma unroll
        for (int kb = 0; kb < 16; kb += 8) {
            int ar = (wm * 16 + g) * AST + kb + tg;
            unsigned a0 = tf32cvt(as[ar]);
            unsigned a1 = tf32cvt(as[ar + 8 * AST]);
            unsigned a2 = tf32cvt(as[ar + 4]);
            unsigned a3 = tf32cvt(as[ar + 8 * AST + 4]);
            #pragma unroll
            for (int j = 0; j < 7; j++) {
                int bcol = wn * 56 + j * 8 + g;
                unsigned b0 = tf32cvt(bs[(kb + tg) * BNNST + bcol]);
                unsigned b1 = tf32cvt(bs[(kb + tg + 4) * BNNST + bcol]);
                mma_tf32(acc[j], a0, a1, a2, a3, b0, b1);
            }
        }
        __syncthreads();
    }

    int r0 = m0 + wm * 16 + g, r1 = r0 + 8;
    float e0 = 0.f, e1 = 0.f;
    if (U != nullptr) {
        float bmv = bmp[0];
        e0 = vm[b * LL + r0] + bmv;
        e1 = vm[b * LL + r1] + bmv;
    }
    #pragma unroll
    for (int j = 0; j < 7; j++) {
        #pragma unroll
        for (int jj = 0; jj < 2; jj++) {
            int col = wn * 56 + j * 8 + tg * 2 + jj;
            if (col >= N) continue;
            float v0 = acc[j][jj], v1 = acc[j][2 + jj];
            if (U != nullptr) {
                float uu = U[b * AA + col], ssv = S[b * AA + col];
                v0 += uu + e0 * ssv;
                v1 += uu + e1 * ssv;
            }
            C[(size_t)r0 * N + col] = v0;
            C[(size_t)r1 * N + col] = v1;
        }
    }
}

// ---------------- scores ----------------
__global__ void scores_kernel(const float* __restrict__ syn, const int* __restrict__ src_mask)
{
    int bh = blockIdx.z;
    int b = bh >> 2, h = bh & 3;
    int i0 = blockIdx.y * 32, j0 = blockIdx.x * 32;
    __shared__ float qs[32][26], ks[32][26];
    int t = threadIdx.x;
    for (int idx = t; idx < 32 * DK; idx += 256) {
        int r = idx / DK, c = idx % DK;
        qs[r][c] = g_q[(size_t)(b * LL + i0 + r) * AA + h * DK + c];
        ks[r][c] = g_k[(size_t)(b * LL + j0 + r) * AA + h * DK + c];
    }
    __syncthreads();
    int i = t >> 3, jb = (t & 7) * 4;
    float qr[DK];
    #pragma unroll
    for (int c = 0; c < DK; c++) qr[c] = qs[i][c];
    #pragma unroll
    for (int jj = 0; jj < 4; jj++) {
        int j = jb + jj;
        float acc = 0.f;
        #pragma unroll
        for (int c = 0; c < DK; c++) acc += qr[c] * ks[j][c];
        float v = acc * 0.2f;
        if (src_mask[b * LL + j0 + j] == 0) v = -1e9f;
        size_t off = ((size_t)(b * HH + h) * LL + (i0 + i)) * LL + (j0 + j);
        v += syn[off];
        g_scores[off] = v;
    }
}

// ---------------- softmax + head folding ----------------
__global__ void softmax_combine_kernel()
{
    int bi = blockIdx.x;
    int t = threadIdx.x;
    __shared__ float red[16];
    float am0 = 0.f, am1 = 0.f, ac0 = 0.f, ac1 = 0.f;
    for (int h = 0; h < HH; h++) {
        size_t base = ((size_t)((bi >> 9) * HH + h) * LL + (bi & 511)) * LL;
        float v0 = g_scores[base + t];
        float v1 = g_scores[base + t + 256];
        float m = fmaxf(v0, v1);
        for (int o = 16; o; o >>= 1) m = fmaxf(m, __shfl_xor_sync(0xffffffffu, m, o));
        if ((t & 31) == 0) red[t >> 5] = m;
        __syncthreads();
        m = red[0];
        #pragma unroll
        for (int i = 1; i < 8; i++) m = fmaxf(m, red[i]);
        float e0 = __expf(v0 - m), e1 = __expf(v1 - m);
        float s = e0 + e1;
        for (int o = 16; o; o >>= 1) s += __shfl_xor_sync(0xffffffffu, s, o);
        if ((t & 31) == 0) red[8 + (t >> 5)] = s;
        __syncthreads();
        s = 0.f;
        #pragma unroll
        for (int i = 0; i < 8; i++) s += red[8 + i];
        float inv = 1.f / s;
        float ch = g_cbuf[h];
        am0 += 0.25f * e0 * inv; am1 += 0.25f * e1 * inv;
        ac0 += ch * e0 * inv;    ac1 += ch * e1 * inv;
        __syncthreads();
    }
    size_t ob = (size_t)bi * LL;
    g_adjm[ob + t] = am0; g_adjm[ob + t + 256] = am1;
    g_adjc[ob + t] = ac0; g_adjc[ob + t + 256] = ac1;
}

// ---------------- um/vm ----------------
__global__ void umvm_kernel()
{
    int w = threadIdx.x >> 5, lane = threadIdx.x & 31;
    int row = blockIdx.x * 8 + w;
    const float* xr = g_x1 + (size_t)row * AA;
    float u = 0.f, v = 0.f;
    for (int c = lane; c < AA; c += 32) {
        float xv = xr[c];
        u += xv * g_b1m[c];
        v += xv * g_b2m[c];
    }
    for (int o = 16; o; o >>= 1) {
        u += __shfl_xor_sync(0xffffffffu, u, o);
        v += __shfl_xor_sync(0xffffffffu, v, o);
    }
    if (lane == 0) { g_um[row] = u; g_vm[row] = v; }
}

// ---------------- S / U ----------------
__global__ void su_kernel()
{
    int b = blockIdx.x;
    int d = threadIdx.x;
    if (d >= AA) return;
    float s = 0.f, u = 0.f;
    for (int j = 0; j < LL; j++) {
        float xv = g_x1[(size_t)(b * LL + j) * AA + d];
        s += xv;
        u += g_um[b * LL + j] * xv;
    }
    g_S[b * AA + d] = s;
    g_U[b * AA + d] = u;
}

// ---------------- concat ----------------
__global__ void concat_kernel()
{
    int idx = blockIdx.x * blockDim.x + threadIdx.x;
    if (idx >= BB * LL * AA) return;
    int row = idx / AA, d = idx % AA;
    g_feats[(size_t)row * (3 * AA) + d]          = g_x [idx];
    g_feats[(size_t)row * (3 * AA) + AA + d]     = g_x1[idx];
    g_feats[(size_t)row * (3 * AA) + 2 * AA + d] = g_x2[idx];
}

// ---------------- pool ----------------
__global__ void pool_kernel(const int* __restrict__ mask_ids)
{
    int b = blockIdx.x;
    __shared__ int redc[128];
    int t = threadIdx.x;
    int cnt = 0;
    for (int j = t; j < LL; j += 128) cnt += mask_ids[b * LL + j];
    redc[t] = cnt;
    __syncthreads();
    for (int o = 64; o; o >>= 1) { if (t < o) redc[t] += redc[t + o]; __syncthreads(); }
    float vl = fmaxf((float)redc[0], 1.f);
    if (t < AA) {
        float s = 0.f;
        for (int j = 0; j < LL; j++) s += g_node[(size_t)(b * LL + j) * AA + t];
        g_pooled[b * AA + t] = s / vl;
    }
}

// ---------------- logits ----------------
__global__ void logits_kernel(const float* __restrict__ cw, const float* __restrict__ cb,
                              float* __restrict__ out)
{
    int t = threadIdx.x;
    if (t >= BB * PP) return;
    int b = t / PP, p = t % PP;
    float s = cb[p];
    for (int d = 0; d < AA; d++) s += g_pooled[b * AA + d] * cw[p * AA + d];
    out[t] = s;
}

// ================================================================
extern "C" void kernel_launch(void* const* d_in, const int* in_sizes, int n_in,
                              void* d_out, int out_size)
{
    const float* seq     = (const float*)d_in[0];
    const float* syn     = (const float*)d_in[1];
    const float* ln_a    = (const float*)d_in[2];
    const float* ln_b    = (const float*)d_in[3];
    const float* Wxx_w   = (const float*)d_in[4];
    const float* Wxx_b   = (const float*)d_in[5];
    const float* q_w     = (const float*)d_in[6];
    const float* q_b     = (const float*)d_in[7];
    const float* k_w     = (const float*)d_in[8];
    const float* k_b     = (const float*)d_in[9];
    const float* W_w     = (const float*)d_in[10];
    const float* W_b     = (const float*)d_in[11];
    const float* Wx_w    = (const float*)d_in[12];
    const float* Wx_b    = (const float*)d_in[13];
    const float* agg_w   = (const float*)d_in[14];
    const float* agg_b   = (const float*)d_in[15];
    const float* cls_w   = (const float*)d_in[16];
    const float* cls_b   = (const float*)d_in[17];
    const int*   mask_ids= (const int*)d_in[18];
    const int*   src_mask= (const int*)d_in[19];
    float* out = (float*)d_out;

    float *p_seqn, *p_x, *p_Ax, *p_x1, *p_x2, *p_feats, *p_node;
    float *p_adjm, *p_adjc, *p_U, *p_S, *p_vm, *p_bm, *p_q, *p_k;
    cudaGetSymbolAddress((void**)&p_seqn, g_seqn);
    cudaGetSymbolAddress((void**)&p_x,    g_x);
    cudaGetSymbolAddress((void**)&p_q,    g_q);
    cudaGetSymbolAddress((void**)&p_k,    g_k);
    cudaGetSymbolAddress((void**)&p_Ax,   g_Ax);
    cudaGetSymbolAddress((void**)&p_x1,   g_x1);
    cudaGetSymbolAddress((void**)&p_x2,   g_x2);
    cudaGetSymbolAddress((void**)&p_feats,g_feats);
    cudaGetSymbolAddress((void**)&p_node, g_node);
    cudaGetSymbolAddress((void**)&p_adjm, g_adjm);
    cudaGetSymbolAddress((void**)&p_adjc, g_adjc);
    cudaGetSymbolAddress((void**)&p_U,    g_U);
    cudaGetSymbolAddress((void**)&p_S,    g_S);
    cudaGetSymbolAddress((void**)&p_vm,   g_vm);
    cudaGetSymbolAddress((void**)&p_bm,   g_bm);

    const int MROWS = BB * LL;
    dim3 nt_grid(1, MROWS / BM);            // 256 blocks
    dim3 nn_grid(1, LL / BM, BB);           // 256 blocks

    pre_kernel<<<1, 128>>>(Wx_w, Wx_b);
    ln_kernel<<<MROWS, 256>>>(seq, ln_a, ln_b);

    gemm_nt_tc<<<nt_grid, 128>>>(p_seqn, Wxx_w, Wxx_b, p_x, MROWS, AA, DD, 0);
    gemm_nt_tc<<<nt_grid, 128>>>(p_x, q_w, q_b, p_q, MROWS, AA, AA, 0);
    gemm_nt_tc<<<nt_grid, 128>>>(p_x, k_w, k_b, p_k, MROWS, AA, AA, 0);

    scores_kernel<<<dim3(LL / 32, LL / 32, BB * HH), 256>>>(syn, src_mask);
    softmax_combine_kernel<<<MROWS, 256>>>();

    gemm_nn_b_tc<<<nn_grid, 128>>>(p_adjm, p_x, p_Ax, AA,
                                   nullptr, nullptr, nullptr, nullptr);
    gemm_nt_tc<<<nt_grid, 128>>>(p_Ax, W_w, W_b, p_x1, MROWS, AA, AA, 1);

    umvm_kernel<<<MROWS / 8, 256>>>();
    su_kernel<<<BB, 128>>>();

    gemm_nn_b_tc<<<nn_grid, 128>>>(p_adjc, p_x1, p_Ax, AA,
                                   p_U, p_S, p_vm, p_bm);
    gemm_nt_tc<<<nt_grid, 128>>>(p_Ax, W_w, W_b, p_x2, MROWS, AA, AA, 1);

    concat_kernel<<<(BB * LL * AA + 255) / 256, 256>>>();
    gemm_nt_tc<<<nt_grid, 128>>>(p_feats, agg_w, agg_b, p_node, MROWS, AA, 3 * AA, 1);

    pool_kernel<<<BB, 128>>>(mask_ids);
    logits_kernel<<<1, 64>>>(cls_w, cls_b, out);
}